// round 10
// baseline (speedup 1.0000x reference)
#include <cuda_runtime.h>
#include <cuda_bf16.h>
#include <cstdint>

// SparseBoundaryContent: x [16, 512, 64] f32.
// boundary(i,j) = (x[i]+x[j])/2 on masked cells, content(i,j) = max(x[i..j])
// on masked cells, 0 elsewhere.
// Output layout (flat f32): [boundary B*D*N*N][content B*D*N*N][mask B*N*N].
//
// R9: ZERO-TEMPLATE design. A 16KB smem zero tile is written once per CTA and
// then only READ (by TMA bulk stores that blanket each output tile with
// zeros). The 1104 masked values per map are then STG'd directly over the
// just-written (L2-hot) lines. No per-row zero-fill, no scatter tile, no
// buffer hazards. RPC=4 rows/CTA, ~18KB smem -> high occupancy.

#define NB 16
#define ND 512
#define NN 64
#define NCELLS 4096          // 64*64 cells per (b,d) row
#define NMASKED 1104         // masked cells per tile (incl. diagonal)
#define RPC 4                // rows per CTA

constexpr bool cell_mask_ct(int i, int j) {
    int d = j - i;
    if (d < 0)  return false;
    if (d <= 15) return true;                              // stride-1 offsets 0..15
    if (d <= 31) return (d & 1) && !(i & 1);               // stride-2: odd 17..31, i even
    return (d >= 35) && ((d & 3) == 3) && !(i & 3);        // stride-4: 35,39,..,63, i%4==0
}

struct MaskTab { float m[NCELLS]; };
constexpr MaskTab gen_mask() {
    MaskTab t{};
    for (int i = 0; i < NN; i++)
        for (int j = 0; j < NN; j++)
            t.m[i * NN + j] = cell_mask_ct(i, j) ? 1.0f : 0.0f;
    return t;
}
__device__ constexpr MaskTab g_mask = gen_mask();

struct Meta { unsigned int m[NMASKED]; };
constexpr Meta gen_meta() {
    Meta t{};
    int cnt = 0;
    for (int i = 0; i < NN; i++) {
        for (int j = 0; j < NN; j++) {
            if (!cell_mask_ct(i, j)) continue;
            int len = j - i + 1;
            int k = 0;
            while ((1 << (k + 1)) <= len) k++;             // floor(log2(len))
            int ri = j + 1 - (1 << k);
            unsigned offL = (unsigned)(k * NN + i);
            unsigned offR = (unsigned)(k * NN + ri);
            t.m[cnt++] = (unsigned)(i * NN + j) | (offL << 12) | (offR << 21);
        }
    }
    return t;
}
__device__ constexpr Meta g_meta = gen_meta();

__device__ __forceinline__ uint32_t smem_u32(const void* p) {
    uint32_t a;
    asm("{ .reg .u64 t; cvta.to.shared.u64 t, %1; cvt.u32.u64 %0, t; }"
        : "=r"(a) : "l"(p));
    return a;
}

__global__ void __launch_bounds__(256)
sbc_kernel(const float* __restrict__ x,
           float* __restrict__ boundary,
           float* __restrict__ content,
           float* __restrict__ mask_out)
{
    __shared__ float Mf[7 * NN];                   // sparse max table
    __shared__ alignas(128) float zt[NCELLS];      // 16KB ZERO TEMPLATE (immutable)

    const int bd0 = blockIdx.x * RPC;
    const int tid = threadIdx.x;
    const int wid = tid >> 5;
    const int lid = tid & 31;

    // Write the zero template once; after the fence it is only ever read.
    const float4 z = make_float4(0.f, 0.f, 0.f, 0.f);
    #pragma unroll
    for (int p = 0; p < 4; p++)
        reinterpret_cast<float4*>(zt)[p * 256 + tid] = z;
    asm volatile("fence.proxy.async.shared::cta;" ::: "memory");

    // Preload this thread's 5 meta descriptors (reused every row).
    unsigned mreg[5];
    #pragma unroll
    for (int p = 0; p < 5; p++) {
        int idx = p * 256 + tid;
        mreg[p] = (idx < NMASKED) ? g_meta.m[idx] : 0xFFFFFFFFu;
    }

    // CTAs holding a d==0 row emit the broadcast mask slice for their batch.
    if ((bd0 & (ND - 1)) == 0) {
        float* mp = mask_out + (size_t)(bd0 >> 9) * NCELLS;
        #pragma unroll
        for (int p = 0; p < 4; p++) {
            const int c0 = (p * 256 + tid) * 4;
            *reinterpret_cast<float4*>(mp + c0) =
                *reinterpret_cast<const float4*>(&g_mask.m[c0]);
        }
    }
    __syncthreads();   // template visible to async proxy before any bulk issue

    for (int r = 0; r < RPC; r++) {
        const int bd = bd0 + r;
        float* gb = boundary + (size_t)bd * NCELLS;
        float* gc = content  + (size_t)bd * NCELLS;

        // Thread 224 (warp 7): blanket both output tiles with zeros via the
        // async proxy, then wait until the writes are globally visible.
        // Warp 0: concurrently rebuild the sparse-max table for this row.
        if (tid == 224) {
            const uint32_t sz = smem_u32(zt);
            asm volatile("cp.async.bulk.global.shared::cta.bulk_group [%0], [%1], %2;"
                         :: "l"(gb), "r"(sz), "n"(NCELLS * 4) : "memory");
            asm volatile("cp.async.bulk.global.shared::cta.bulk_group [%0], [%1], %2;"
                         :: "l"(gc), "r"(sz), "n"(NCELLS * 4) : "memory");
            asm volatile("cp.async.bulk.commit_group;" ::: "memory");
            asm volatile("cp.async.bulk.wait_group 0;" ::: "memory");
        }
        if (wid == 0) {
            const float* xr = x + (size_t)bd * NN;
            Mf[lid]      = xr[lid];
            Mf[lid + 32] = xr[lid + 32];
            __syncwarp();
            #pragma unroll
            for (int k = 1; k < 7; k++) {
                const int h  = 1 << (k - 1);
                const int e1 = lid + 32;
                int o0 = lid + h; if (o0 > 63) o0 = 63;
                int o1 = e1  + h; if (o1 > 63) o1 = 63;
                const float a = fmaxf(Mf[(k - 1) * NN + lid], Mf[(k - 1) * NN + o0]);
                const float b = fmaxf(Mf[(k - 1) * NN + e1],  Mf[(k - 1) * NN + o1]);
                Mf[k * NN + lid] = a;
                Mf[k * NN + e1]  = b;
                __syncwarp();
            }
        }
        __syncthreads();   // Mf ready AND zero blanket committed to memory

        // Overwrite the 1104 masked cells of each map directly (L2-hot lines).
        #pragma unroll
        for (int p = 0; p < 5; p++) {
            const unsigned m = mreg[p];
            if (m != 0xFFFFFFFFu) {
                const int cell = m & 4095u;
                const int i    = cell >> 6;
                const int j    = cell & 63;
                gb[cell] = (Mf[i] + Mf[j]) * 0.5f;
                gc[cell] = fmaxf(Mf[(m >> 12) & 511u], Mf[(m >> 21) & 511u]);
            }
        }
        __syncthreads();   // all Mf readers done before next row rebuilds it
    }
}

extern "C" void kernel_launch(void* const* d_in, const int* in_sizes, int n_in,
                              void* d_out, int out_size) {
    const float* x = (const float*)d_in[0];
    float* out = (float*)d_out;

    const size_t map_elems = (size_t)NB * ND * NN * NN;   // 33,554,432
    float* boundary = out;
    float* content  = out + map_elems;
    float* mask_out = out + 2 * map_elems;

    sbc_kernel<<<(NB * ND) / RPC, 256>>>(x, boundary, content, mask_out);
}

// round 11
// speedup vs baseline: 1.1237x; 1.1237x over previous
#include <cuda_runtime.h>
#include <cuda_bf16.h>
#include <cstdint>

// SparseBoundaryContent: x [16, 512, 64] f32.
// boundary(i,j) = (x[i]+x[j])/2 on masked cells, content(i,j) = max(x[i..j])
// on masked cells, 0 elsewhere.
// Output layout (flat f32): [boundary B*D*N*N][content B*D*N*N][mask B*N*N].
//
// R10: HALF-TILE CTAs. Each CTA builds half a (b,d) tile pair (8KB+8KB smem),
// scatters only its half's masked cells, and bulk-stores 2x8KB via the async
// proxy. Smaller grain -> shorter CTA critical path, 8 CTAs/SM, more
// outstanding TMA stores per SM.

#define NB 16
#define ND 512
#define NN 64
#define NCELLS 4096          // 64*64 cells per (b,d) row
#define HCELLS 2048          // cells per half-tile
#define NMASKED 1104         // masked cells per tile (incl. diagonal)
#define SPLIT 676            // meta entries with i < 32 (half 0)

constexpr bool cell_mask_ct(int i, int j) {
    int d = j - i;
    if (d < 0)  return false;
    if (d <= 15) return true;                              // stride-1 offsets 0..15
    if (d <= 31) return (d & 1) && !(i & 1);               // stride-2: odd 17..31, i even
    return (d >= 35) && ((d & 3) == 3) && !(i & 3);        // stride-4: 35,39,..,63, i%4==0
}

struct MaskTab { float m[NCELLS]; };
constexpr MaskTab gen_mask() {
    MaskTab t{};
    for (int i = 0; i < NN; i++)
        for (int j = 0; j < NN; j++)
            t.m[i * NN + j] = cell_mask_ct(i, j) ? 1.0f : 0.0f;
    return t;
}
__device__ constexpr MaskTab g_mask = gen_mask();

struct Meta { unsigned int m[NMASKED]; };
constexpr Meta gen_meta() {
    Meta t{};
    int cnt = 0;
    for (int i = 0; i < NN; i++) {                         // i-major: half 0 first
        for (int j = 0; j < NN; j++) {
            if (!cell_mask_ct(i, j)) continue;
            int len = j - i + 1;
            int k = 0;
            while ((1 << (k + 1)) <= len) k++;             // floor(log2(len))
            int ri = j + 1 - (1 << k);
            unsigned offL = (unsigned)(k * NN + i);
            unsigned offR = (unsigned)(k * NN + ri);
            t.m[cnt++] = (unsigned)(i * NN + j) | (offL << 12) | (offR << 21);
        }
    }
    return t;
}
__device__ constexpr Meta g_meta = gen_meta();

constexpr int count_half0() {
    int c = 0;
    for (int i = 0; i < 32; i++)
        for (int j = 0; j < NN; j++)
            if (cell_mask_ct(i, j)) c++;
    return c;
}
static_assert(count_half0() == SPLIT, "half-0 meta split mismatch");

__device__ __forceinline__ uint32_t smem_u32(const void* p) {
    uint32_t a;
    asm("{ .reg .u64 t; cvta.to.shared.u64 t, %1; cvt.u32.u64 %0, t; }"
        : "=r"(a) : "l"(p));
    return a;
}

__global__ void __launch_bounds__(256)
sbc_kernel(const float* __restrict__ x,
           float* __restrict__ boundary,
           float* __restrict__ content,
           float* __restrict__ mask_out)
{
    __shared__ float Mf[7 * NN];                 // sparse max table
    __shared__ alignas(128) float bt[HCELLS];    // boundary half-tile (8 KB)
    __shared__ alignas(128) float ct[HCELLS];    // content half-tile  (8 KB)

    const int bd   = blockIdx.x >> 1;            // (b,d) row
    const int half = blockIdx.x & 1;             // 0: i<32, 1: i>=32
    const int tid  = threadIdx.x;

    // Issue the x-row load FIRST (hide DRAM latency under zero-fill).
    float xv = 0.0f;
    if (tid < NN) xv = x[(size_t)bd * NN + tid];

    // Zero-fill both half-tiles (4 float4 per thread).
    const float4 z = make_float4(0.f, 0.f, 0.f, 0.f);
    #pragma unroll
    for (int p = 0; p < 2; p++) {
        reinterpret_cast<float4*>(bt)[p * 256 + tid] = z;
        reinterpret_cast<float4*>(ct)[p * 256 + tid] = z;
    }

    if (tid < NN) Mf[tid] = xv;
    __syncthreads();

    // Sparse max table: Mf[k*64+i] = max x[i .. min(i+2^k-1, 63)]
    #pragma unroll
    for (int k = 1; k < 7; k++) {
        if (tid < NN) {
            int o = tid + (1 << (k - 1));
            if (o > NN - 1) o = NN - 1;
            Mf[k * NN + tid] = fmaxf(Mf[(k - 1) * NN + tid], Mf[(k - 1) * NN + o]);
        }
        __syncthreads();
    }

    // Scatter this half's masked cells (half0: [0,676), half1: [676,1104)).
    const int start = half ? SPLIT : 0;
    const int end   = half ? NMASKED : SPLIT;
    const int base  = half * HCELLS;
    #pragma unroll
    for (int p = 0; p < 3; p++) {
        const int idx = start + p * 256 + tid;
        if (idx < end) {
            const unsigned m    = g_meta.m[idx];
            const int      cell = (m & 4095u) - base;      // local to this half
            const int      gi   = (m & 4095u) >> 6;
            const int      gj   = (m & 4095u) & 63;
            bt[cell] = (Mf[gi] + Mf[gj]) * 0.5f;
            ct[cell] = fmaxf(Mf[(m >> 12) & 511u], Mf[(m >> 21) & 511u]);
        }
    }

    asm volatile("fence.proxy.async.shared::cta;" ::: "memory");
    __syncthreads();

    // Bulk-store both 8 KB half-tiles via the async proxy.
    if (tid == 0) {
        const uint32_t sb = smem_u32(bt);
        const uint32_t sc = smem_u32(ct);
        float* gb = boundary + (size_t)bd * NCELLS + base;
        float* gc = content  + (size_t)bd * NCELLS + base;
        asm volatile("cp.async.bulk.global.shared::cta.bulk_group [%0], [%1], %2;"
                     :: "l"(gb), "r"(sb), "n"(HCELLS * 4) : "memory");
        asm volatile("cp.async.bulk.global.shared::cta.bulk_group [%0], [%1], %2;"
                     :: "l"(gc), "r"(sc), "n"(HCELLS * 4) : "memory");
        asm volatile("cp.async.bulk.commit_group;" ::: "memory");
    }

    // Half-tiles of the broadcast mask slice (only bd % ND == 0 CTAs).
    if ((bd & (ND - 1)) == 0) {
        float* mp = mask_out + (size_t)(bd >> 9) * NCELLS + base;
        const float* ms = g_mask.m + base;
        #pragma unroll
        for (int p = 0; p < 2; p++) {
            const int c0 = (p * 256 + tid) * 4;
            *reinterpret_cast<float4*>(mp + c0) =
                *reinterpret_cast<const float4*>(ms + c0);
        }
    }

    // Drain before CTA teardown (smem reuse safety).
    if (tid == 0)
        asm volatile("cp.async.bulk.wait_group 0;" ::: "memory");
}

extern "C" void kernel_launch(void* const* d_in, const int* in_sizes, int n_in,
                              void* d_out, int out_size) {
    const float* x = (const float*)d_in[0];
    float* out = (float*)d_out;

    const size_t map_elems = (size_t)NB * ND * NN * NN;   // 33,554,432
    float* boundary = out;
    float* content  = out + map_elems;
    float* mask_out = out + 2 * map_elems;

    sbc_kernel<<<NB * ND * 2, 256>>>(x, boundary, content, mask_out);
}